// round 12
// baseline (speedup 1.0000x reference)
#include <cuda_runtime.h>
#include <cuda_fp16.h>
#include <mma.h>
#include <math.h>

using namespace nvcuda;

#define BB 32
#define CC 64
#define FH 80
#define FW 200
#define HW 16000
#define LANES 64
#define SP 36
#define PE 78
#define J_TOT 2304
#define M_TOT 2048
#define MB 16                       // m's per kDE block

// ---------------- scratch ----------------
__device__ __half d_featT[BB * HW * CC];          // (B,H,W,C) fp16
__device__ float  d_pool8[BB * 2000 * CC];        // partial pool [b][q][c]
__device__ __half d_xfh[BB * CC * 250];           // pooled context fp16 [b][c][r]
__device__ float  d_weffp[8 * CC * J_TOT];        // fold partials [ck][o][j]
__device__ float  d_beffp[CC * 8];
__device__ __half d_weffh[J_TOT * CC];            // folded weight fp16 [j][o]
__device__ float  d_beff[CC];
__device__ float  d_g[M_TOT * CC];                // attention output [m][c]

__device__ __forceinline__ float warpMaxf(float a) {
#pragma unroll
    for (int off = 16; off > 0; off >>= 1) a = fmaxf(a, __shfl_xor_sync(0xffffffffu, a, off));
    return a;
}
__device__ __forceinline__ float warpSumf(float a) {
#pragma unroll
    for (int off = 16; off > 0; off >>= 1) a += __shfl_xor_sync(0xffffffffu, a, off);
    return a;
}

// ==================== k1: [kC fold | kA transpose+pool] heterogeneous grid =========
__global__ void k1_feat_and_fold(const float* __restrict__ feat,
                                 const float* __restrict__ w1,
                                 const float* __restrict__ b1,
                                 const float* __restrict__ fw) {
    __shared__ float tile[64][65];
    __shared__ float red[256];
    int bid = blockIdx.x;
    int tid = threadIdx.x;

    if (bid >= 512) {
        int ab = bid - 512;
        int bx = ab % 250, b = ab / 250;
        const float4* src = (const float4*)(feat + (size_t)b * CC * HW + bx * 64);
#pragma unroll
        for (int i = tid; i < 1024; i += 256) {
            int c = i >> 4, x4 = i & 15;
            float4 v = src[(size_t)c * (HW / 4) + x4];
            tile[c][x4 * 4 + 0] = v.x; tile[c][x4 * 4 + 1] = v.y;
            tile[c][x4 * 4 + 2] = v.z; tile[c][x4 * 4 + 3] = v.w;
        }
        __syncthreads();
#pragma unroll
        for (int i = tid; i < 512; i += 256) {
            int row = i >> 3, seg = i & 7;
            __align__(16) __half h[8];
#pragma unroll
            for (int j = 0; j < 8; j++) h[j] = __float2half_rn(tile[seg * 8 + j][row]);
            *(uint4*)(d_featT + ((size_t)b * HW + bx * 64 + row) * CC + seg * 8) = *(uint4*)h;
        }
#pragma unroll
        for (int i = tid; i < 512; i += 256) {
            int q = i >> 6, c = i & 63;
            float s = 0.f;
#pragma unroll
            for (int j = 0; j < 8; j++) s += tile[c][q * 8 + j];
            d_pool8[((size_t)b * 2000 + bx * 8 + q) * CC + c] = s;
        }
    } else {
        int o = bid & 63, ck = bid >> 6;
        int cmBase = ck * 8;
        float* fc_s = &tile[0][0];
        fc_s[tid] = fw[o * 2048 + cmBase * 32 + tid];
        __syncthreads();
        int cin = tid & 63, s0 = tid >> 6;
        float acc[9];
#pragma unroll
        for (int it = 0; it < 9; it++) acc[it] = 0.f;
#pragma unroll
        for (int cm8 = 0; cm8 < 8; cm8++) {
            int cm = cmBase + cm8;
            float wv[5];
#pragma unroll
            for (int k = 0; k < 5; k++) wv[k] = __ldg(w1 + (cm * CC + cin) * 5 + k);
            const float* frow = fc_s + cm8 * 32;
#pragma unroll
            for (int it = 0; it < 9; it++) {
                int s = s0 + it * 4;
#pragma unroll
                for (int k = 0; k < 5; k++) {
                    int t = s - k;
                    if ((unsigned)t < 32u) acc[it] += frow[t] * wv[k];
                }
            }
        }
#pragma unroll
        for (int it = 0; it < 9; it++)
            d_weffp[(size_t)ck * (CC * J_TOT) + (size_t)o * J_TOT + (tid + it * 256)] = acc[it];
        red[tid] = fc_s[tid] * b1[cmBase + (tid >> 5)];
        __syncthreads();
        for (int st = 128; st > 0; st >>= 1) {
            if (tid < st) red[tid] += red[tid + st];
            __syncthreads();
        }
        if (tid == 0) d_beffp[o * 8 + ck] = red[0];
    }
}

// ==================== k2: [kC2 weight-reduce | kA2 pool-reduce] ====================
__global__ void k2_reduce(const float* __restrict__ fb) {
    __shared__ float t_s[64][9];
    int bid = blockIdx.x;
    int tid = threadIdx.x;

    if (bid >= 288) {
        int pb = bid - 288;
        int b = pb / 63, rc = pb % 63;
        int rl = tid >> 6, c = tid & 63;
        int r = rc * 4 + rl;
        if (r < 250) {
            int rh = r / 25, rw = r - rh * 25;
            float acc = 0.f;
#pragma unroll
            for (int dh = 0; dh < 8; dh++)
                acc += d_pool8[((size_t)b * 2000 + (rh * 8 + dh) * 25 + rw) * CC + c];
            d_xfh[((size_t)b * CC + c) * 250 + r] = __float2half_rn(acc * (1.0f / 64.0f));
        }
    } else {
        int jb = bid % 36, og = bid / 36;
#pragma unroll
        for (int i = tid; i < 512; i += 256) {
            int ol = i >> 6, jl = i & 63;
            float a = 0.f;
#pragma unroll
            for (int ck = 0; ck < 8; ck++)
                a += d_weffp[(size_t)ck * (CC * J_TOT) + (size_t)(og * 8 + ol) * J_TOT + jb * 64 + jl];
            t_s[jl][ol] = a;
        }
        __syncthreads();
        {
            int jl = tid >> 2, op = tid & 3;
            __half2 h = __floats2half2_rn(t_s[jl][2 * op], t_s[jl][2 * op + 1]);
            ((__half2*)d_weffh)[(size_t)(jb * 64 + jl) * 32 + og * 4 + op] = h;
        }
        if (jb == 0 && og == 0 && tid < CC) {
            float s = 0.f;
#pragma unroll
            for (int ck = 0; ck < 8; ck++) s += d_beffp[tid * 8 + ck];
            d_beff[tid] = fb[tid] + s;
        }
    }
}

// ==================== kDE: gather + wmma x_p + attention, fused ====================
// 128 blocks, 512 threads (16 warps). Block = 16 m's = 2 lane-groups of one b.
// dyn smem: rs 73728 (part 16KB aliased) | xf 32000 = 105728 B
__global__ void kDE(const float* __restrict__ prior) {
    extern __shared__ char smraw[];
    __half* rs = (__half*)smraw;                           // 16*2304*2 = 73728 B
    __half2* xf_s = (__half2*)(smraw + 73728);             // 64*125 half2 = 32000 B
    __shared__ int offs0[576], offs1[576], offs2[576], offs3[576];
    __shared__ float xp_s[MB * 64];
    __shared__ float g_buf[MB * 64];

    int m0 = blockIdx.x * MB;
    int b = m0 >> 6;
    int tid = threadIdx.x;
    int w = tid >> 5, lane = tid & 31;

    // full xf slice: 64c x 250r fp16 = 32000 B = 2000 float4 (issued early)
    const float4* xsrc = (const float4*)(d_xfh + (size_t)b * (CC * 250));
#pragma unroll
    for (int i = tid; i < 2000; i += 512) ((float4*)xf_s)[i] = xsrc[i];

    // coordinates -> offsets for 16 m x 36 s
    for (int i = tid; i < 576; i += 512) {
        int ml = i / 36, s = i - ml * 36;
        float px = prior[(size_t)(m0 + ml) * PE + 6 + 2 * s];
        float xs = fminf(px * 0.25f, 199.0f);
        int xc = (int)ceilf(xs), xf_ = (int)floorf(xs);
        double py = 319.0 - (320.0 / 71.0) * (double)(2 * s);
        float ys = fminf((float)py * 0.25f, 79.0f);
        int yc = (int)ceilf(ys), yf_ = (int)floorf(ys);
        offs0[i] = (yc * FW + xc) * CC;
        offs1[i] = (yc * FW + xf_) * CC;
        offs2[i] = (yf_ * FW + xc) * CC;
        offs3[i] = (yf_ * FW + xf_) * CC;
    }
    __syncthreads();

    // gather: warp per point-quad, lane = channel-pair
    const __half2* f2 = (const __half2*)(d_featT + (size_t)b * HW * CC);
    __half2* rs2 = (__half2*)rs;
#pragma unroll 2
    for (int i = w; i < 576; i += 16) {
        int ml = i / 36, s = i - ml * 36;
        float2 v0 = __half22float2(f2[(offs0[i] >> 1) + lane]);
        float2 v1 = __half22float2(f2[(offs1[i] >> 1) + lane]);
        float2 v2 = __half22float2(f2[(offs2[i] >> 1) + lane]);
        float2 v3 = __half22float2(f2[(offs3[i] >> 1) + lane]);
        float2 r;
        r.x = (v0.x + v1.x + v2.x + v3.x) * 0.25f;
        r.y = (v0.y + v1.y + v2.y + v3.y) * 0.25f;
        rs2[((ml * J_TOT + s * CC) >> 1) + lane] = __float22half2_rn(r);
    }
    __syncthreads();

    // wmma m16n16k16: warp w -> otile = w>>2 (16 o's), kq = w&3 (36 ksteps)
    float* part = (float*)rs;   // aliased AFTER all rs reads complete (sync below)
    {
        int otile = w >> 2, kq = w & 3;
        wmma::fragment<wmma::matrix_a, 16, 16, 16, __half, wmma::row_major> af;
        wmma::fragment<wmma::matrix_b, 16, 16, 16, __half, wmma::row_major> bf;
        wmma::fragment<wmma::accumulator, 16, 16, 16, float> cf;
        wmma::fill_fragment(cf, 0.0f);
        for (int ks = kq * 36; ks < kq * 36 + 36; ks++) {
            int k0 = ks * 16;
            wmma::load_matrix_sync(af, rs + k0, J_TOT);
            wmma::load_matrix_sync(bf, d_weffh + (size_t)k0 * CC + otile * 16, CC);
            wmma::mma_sync(cf, af, bf, cf);
        }
        __syncthreads();   // all warps done READING rs; accum lives in registers
        wmma::store_matrix_sync(part + w * 256, cf, 16, wmma::mem_row_major);
    }
    __syncthreads();

    // combine k-quarters + bias -> xp_s[m][o]
    for (int i = tid; i < MB * 64; i += 512) {
        int m = i >> 6, o = i & 63;
        int ot = o >> 4, ol = o & 15;
        float v = part[(ot * 4 + 0) * 256 + m * 16 + ol]
                + part[(ot * 4 + 1) * 256 + m * 16 + ol]
                + part[(ot * 4 + 2) * 256 + m * 16 + ol]
                + part[(ot * 4 + 3) * 256 + m * 16 + ol] + d_beff[o];
        xp_s[i] = v;
    }
    __syncthreads();

    // attention: warp w handles m = m0 + w (16 warps, 16 m's)
    const float* xpw = xp_s + w * 64;
    int pr[4]; bool ok[4];
#pragma unroll
    for (int k = 0; k < 4; k++) {
        int p = lane + 32 * k;
        ok[k] = p < 125;
        pr[k] = ok[k] ? p : 124;
    }
    float sx[4] = {0, 0, 0, 0}, sy[4] = {0, 0, 0, 0};
    for (int c = 0; c < 64; c++) {
        float xc = xpw[c];
        const __half2* row = xf_s + c * 125;
#pragma unroll
        for (int k = 0; k < 4; k++) {
            float2 v = __half22float2(row[pr[k]]);
            sx[k] += xc * v.x;
            sy[k] += xc * v.y;
        }
    }
    float mx = -INFINITY;
#pragma unroll
    for (int k = 0; k < 4; k++) {
        sx[k] = ok[k] ? sx[k] * 0.125f : -INFINITY;
        sy[k] = ok[k] ? sy[k] * 0.125f : -INFINITY;
        mx = fmaxf(mx, fmaxf(sx[k], sy[k]));
    }
    mx = warpMaxf(mx);
    float wx[4], wy[4], wsum = 0.f;
#pragma unroll
    for (int k = 0; k < 4; k++) {
        wx[k] = ok[k] ? expf(sx[k] - mx) : 0.f;
        wy[k] = ok[k] ? expf(sy[k] - mx) : 0.f;
        wsum += wx[k] + wy[k];
    }
    wsum = warpSumf(wsum);
    float inv = 1.0f / wsum;
#pragma unroll
    for (int k = 0; k < 4; k++) { wx[k] *= inv; wy[k] *= inv; }

    for (int c = 0; c < 64; c++) {
        const __half2* row = xf_s + c * 125;
        float a = 0.f;
#pragma unroll
        for (int k = 0; k < 4; k++) {
            float2 v = __half22float2(row[pr[k]]);
            a += wx[k] * v.x + wy[k] * v.y;
        }
        a = warpSumf(a);
        if (lane == 0) g_buf[w * 64 + c] = a;
    }
    __syncthreads();
    for (int i = tid; i < MB * 64; i += 512) {
        int ml = i >> 6, c = i & 63;
        d_g[(size_t)(m0 + ml) * CC + c] = g_buf[i];
    }
}

// ==================== kE3: conv1x1 + relu + residual, 2 batches per block ==========
// grid (16, 8), 512 threads: 16 warps = 8 o's x 2 K-halves; each warp serves 2 b's.
__global__ void kE3_out(const float* __restrict__ w1x1, const float* __restrict__ b1x1,
                        const float* __restrict__ prior, float* __restrict__ out) {
    __shared__ float g_s[2][4096];
    __shared__ float part_s[2][16];
    __shared__ float gr_s[2][8];
    int bp = blockIdx.x, og = blockIdx.y;
    int b0 = bp * 2;
    int tid = threadIdx.x, w = tid >> 5, lid = tid & 31;
    // load both batches' g: 2048 float4 over 512 threads
    const float4* gsrc = (const float4*)(d_g + (size_t)b0 * 4096);
#pragma unroll
    for (int i = tid; i < 2048; i += 512) ((float4*)g_s)[i] = gsrc[i];
    __syncthreads();
    int ol = w >> 1, kh = w & 1;
    int o = og * 8 + ol;
    const float4* wr = (const float4*)(w1x1 + (size_t)o * 4096) + kh * 512;
    const float4* g0 = ((const float4*)g_s[0]) + kh * 512;
    const float4* g1 = ((const float4*)g_s[1]) + kh * 512;
    float a0 = 0.f, a1 = 0.f;
#pragma unroll 4
    for (int j4 = lid; j4 < 512; j4 += 32) {
        float4 wv = wr[j4];
        float4 v0 = g0[j4];
        float4 v1 = g1[j4];
        a0 += wv.x * v0.x + wv.y * v0.y + wv.z * v0.z + wv.w * v0.w;
        a1 += wv.x * v1.x + wv.y * v1.y + wv.z * v1.z + wv.w * v1.w;
    }
    a0 = warpSumf(a0);
    a1 = warpSumf(a1);
    if (lid == 0) { part_s[0][w] = a0; part_s[1][w] = a1; }
    __syncthreads();
    if (tid < 16) {
        int i = tid >> 3, t = tid & 7;
        gr_s[i][t] = fmaxf(part_s[i][2 * t] + part_s[i][2 * t + 1] + b1x1[og * 8 + t], 0.f);
    }
    __syncthreads();
    for (int e = tid; e < 2 * 8 * PE; e += 512) {
        int i = e / (8 * PE);
        int rem = e - i * (8 * PE);
        int jl = rem / PE, t = rem - jl * PE;
        size_t idx = (size_t)(b0 + i) * (64 * PE) + (size_t)(og * 8 + jl) * PE + t;
        out[idx] = gr_s[i][jl] + prior[idx];
    }
}

// ---------------- host launcher ----------------------------------------------------
extern "C" void kernel_launch(void* const* d_in, const int* in_sizes, int n_in,
                              void* d_out, int out_size) {
    const float* feature = (const float*)d_in[0];
    const float* prior   = (const float*)d_in[1];
    const float* w1      = (const float*)d_in[2];
    const float* b1      = (const float*)d_in[3];
    const float* fw      = (const float*)d_in[4];
    const float* fb      = (const float*)d_in[5];
    const float* w1x1    = (const float*)d_in[6];
    const float* b1x1    = (const float*)d_in[7];
    float* out = (float*)d_out;

    const int kde_smem = 73728 + 32000;   // rs(+part alias) | xf = 105728 B
    cudaFuncSetAttribute(kDE, cudaFuncAttributeMaxDynamicSharedMemorySize, kde_smem);

    k1_feat_and_fold<<<8512, 256>>>(feature, w1, b1, fw);
    k2_reduce<<<2304, 256>>>(fb);
    kDE<<<M_TOT / MB, 512, kde_smem>>>(prior);
    kE3_out<<<dim3(BB / 2, 8), 512>>>(w1x1, b1x1, prior, out);
}

// round 13
// speedup vs baseline: 1.0120x; 1.0120x over previous
#include <cuda_runtime.h>
#include <cuda_fp16.h>
#include <mma.h>
#include <math.h>

using namespace nvcuda;

#define BB 32
#define CC 64
#define FH 80
#define FW 200
#define HW 16000
#define LANES 64
#define SP 36
#define PE 78
#define J_TOT 2304
#define M_TOT 2048
#define MB 16                       // m's per kDE block

// ---------------- scratch ----------------
__device__ __half d_featT[BB * HW * CC];          // (B,H,W,C) fp16
__device__ float  d_pool8[BB * 2000 * CC];        // partial pool [b][q][c]
__device__ __half d_xfh[BB * CC * 250];           // pooled context fp16 [b][c][r]
__device__ float  d_weffp[8 * CC * J_TOT];        // fold partials [ck][o][j]
__device__ float  d_beffp[CC * 8];
__device__ __half d_weffh[J_TOT * CC];            // folded weight fp16 [j][o]
__device__ float  d_beff[CC];
__device__ float  d_g[M_TOT * CC];                // attention output [m][c]

__device__ __forceinline__ float warpMaxf(float a) {
#pragma unroll
    for (int off = 16; off > 0; off >>= 1) a = fmaxf(a, __shfl_xor_sync(0xffffffffu, a, off));
    return a;
}
__device__ __forceinline__ float warpSumf(float a) {
#pragma unroll
    for (int off = 16; off > 0; off >>= 1) a += __shfl_xor_sync(0xffffffffu, a, off);
    return a;
}

// ==================== k1: [kC fold | kA transpose+pool] heterogeneous grid =========
__global__ void k1_feat_and_fold(const float* __restrict__ feat,
                                 const float* __restrict__ w1,
                                 const float* __restrict__ b1,
                                 const float* __restrict__ fw) {
    __shared__ float tile[64][65];
    __shared__ float red[256];
    int bid = blockIdx.x;
    int tid = threadIdx.x;

    if (bid >= 512) {
        int ab = bid - 512;
        int bx = ab % 250, b = ab / 250;
        const float4* src = (const float4*)(feat + (size_t)b * CC * HW + bx * 64);
#pragma unroll
        for (int i = tid; i < 1024; i += 256) {
            int c = i >> 4, x4 = i & 15;
            float4 v = src[(size_t)c * (HW / 4) + x4];
            tile[c][x4 * 4 + 0] = v.x; tile[c][x4 * 4 + 1] = v.y;
            tile[c][x4 * 4 + 2] = v.z; tile[c][x4 * 4 + 3] = v.w;
        }
        __syncthreads();
#pragma unroll
        for (int i = tid; i < 512; i += 256) {
            int row = i >> 3, seg = i & 7;
            __align__(16) __half h[8];
#pragma unroll
            for (int j = 0; j < 8; j++) h[j] = __float2half_rn(tile[seg * 8 + j][row]);
            *(uint4*)(d_featT + ((size_t)b * HW + bx * 64 + row) * CC + seg * 8) = *(uint4*)h;
        }
#pragma unroll
        for (int i = tid; i < 512; i += 256) {
            int q = i >> 6, c = i & 63;
            float s = 0.f;
#pragma unroll
            for (int j = 0; j < 8; j++) s += tile[c][q * 8 + j];
            d_pool8[((size_t)b * 2000 + bx * 8 + q) * CC + c] = s;
        }
    } else {
        int o = bid & 63, ck = bid >> 6;
        int cmBase = ck * 8;
        float* fc_s = &tile[0][0];
        fc_s[tid] = fw[o * 2048 + cmBase * 32 + tid];
        __syncthreads();
        int cin = tid & 63, s0 = tid >> 6;
        float acc[9];
#pragma unroll
        for (int it = 0; it < 9; it++) acc[it] = 0.f;
#pragma unroll
        for (int cm8 = 0; cm8 < 8; cm8++) {
            int cm = cmBase + cm8;
            float wv[5];
#pragma unroll
            for (int k = 0; k < 5; k++) wv[k] = __ldg(w1 + (cm * CC + cin) * 5 + k);
            const float* frow = fc_s + cm8 * 32;
#pragma unroll
            for (int it = 0; it < 9; it++) {
                int s = s0 + it * 4;
#pragma unroll
                for (int k = 0; k < 5; k++) {
                    int t = s - k;
                    if ((unsigned)t < 32u) acc[it] += frow[t] * wv[k];
                }
            }
        }
#pragma unroll
        for (int it = 0; it < 9; it++)
            d_weffp[(size_t)ck * (CC * J_TOT) + (size_t)o * J_TOT + (tid + it * 256)] = acc[it];
        red[tid] = fc_s[tid] * b1[cmBase + (tid >> 5)];
        __syncthreads();
        for (int st = 128; st > 0; st >>= 1) {
            if (tid < st) red[tid] += red[tid + st];
            __syncthreads();
        }
        if (tid == 0) d_beffp[o * 8 + ck] = red[0];
    }
}

// ==================== k2: [kC2 weight-reduce | kA2 pool-reduce] ====================
__global__ void k2_reduce(const float* __restrict__ fb) {
    __shared__ float t_s[64][9];
    int bid = blockIdx.x;
    int tid = threadIdx.x;

    if (bid >= 288) {
        int pb = bid - 288;
        int b = pb / 63, rc = pb % 63;
        int rl = tid >> 6, c = tid & 63;
        int r = rc * 4 + rl;
        if (r < 250) {
            int rh = r / 25, rw = r - rh * 25;
            float acc = 0.f;
#pragma unroll
            for (int dh = 0; dh < 8; dh++)
                acc += d_pool8[((size_t)b * 2000 + (rh * 8 + dh) * 25 + rw) * CC + c];
            d_xfh[((size_t)b * CC + c) * 250 + r] = __float2half_rn(acc * (1.0f / 64.0f));
        }
    } else {
        int jb = bid % 36, og = bid / 36;
#pragma unroll
        for (int i = tid; i < 512; i += 256) {
            int ol = i >> 6, jl = i & 63;
            float a = 0.f;
#pragma unroll
            for (int ck = 0; ck < 8; ck++)
                a += d_weffp[(size_t)ck * (CC * J_TOT) + (size_t)(og * 8 + ol) * J_TOT + jb * 64 + jl];
            t_s[jl][ol] = a;
        }
        __syncthreads();
        {
            int jl = tid >> 2, op = tid & 3;
            __half2 h = __floats2half2_rn(t_s[jl][2 * op], t_s[jl][2 * op + 1]);
            ((__half2*)d_weffh)[(size_t)(jb * 64 + jl) * 32 + og * 4 + op] = h;
        }
        if (jb == 0 && og == 0 && tid < CC) {
            float s = 0.f;
#pragma unroll
            for (int ck = 0; ck < 8; ck++) s += d_beffp[tid * 8 + ck];
            d_beff[tid] = fb[tid] + s;
        }
    }
}

// ==================== kDE: gather + wmma x_p + attention, fused ====================
// 128 blocks, 512 threads (16 warps). Block = 16 m's = 2 lane-groups of one b.
// dyn smem: rs 73728 (part 16KB aliased) | xf 32000 = 105728 B
__global__ void kDE(const float* __restrict__ prior) {
    extern __shared__ char smraw[];
    __half* rs = (__half*)smraw;                           // 16*2304*2 = 73728 B
    __half2* xf_s = (__half2*)(smraw + 73728);             // 64*125 half2 = 32000 B
    __shared__ int offs0[576], offs1[576], offs2[576], offs3[576];
    __shared__ float xp_s[MB * 64];
    __shared__ float g_buf[MB * 64];

    int m0 = blockIdx.x * MB;
    int b = m0 >> 6;
    int tid = threadIdx.x;
    int w = tid >> 5, lane = tid & 31;

    // full xf slice: 64c x 250r fp16 = 32000 B = 2000 float4 (issued early)
    const float4* xsrc = (const float4*)(d_xfh + (size_t)b * (CC * 250));
#pragma unroll
    for (int i = tid; i < 2000; i += 512) ((float4*)xf_s)[i] = xsrc[i];

    // coordinates -> offsets for 16 m x 36 s
    for (int i = tid; i < 576; i += 512) {
        int ml = i / 36, s = i - ml * 36;
        float px = prior[(size_t)(m0 + ml) * PE + 6 + 2 * s];
        float xs = fminf(px * 0.25f, 199.0f);
        int xc = (int)ceilf(xs), xf_ = (int)floorf(xs);
        double py = 319.0 - (320.0 / 71.0) * (double)(2 * s);
        float ys = fminf((float)py * 0.25f, 79.0f);
        int yc = (int)ceilf(ys), yf_ = (int)floorf(ys);
        offs0[i] = (yc * FW + xc) * CC;
        offs1[i] = (yc * FW + xf_) * CC;
        offs2[i] = (yf_ * FW + xc) * CC;
        offs3[i] = (yf_ * FW + xf_) * CC;
    }
    __syncthreads();

    // gather: warp per point-quad, lane = channel-pair
    const __half2* f2 = (const __half2*)(d_featT + (size_t)b * HW * CC);
    __half2* rs2 = (__half2*)rs;
#pragma unroll 4
    for (int i = w; i < 576; i += 16) {
        int ml = i / 36, s = i - ml * 36;
        float2 v0 = __half22float2(f2[(offs0[i] >> 1) + lane]);
        float2 v1 = __half22float2(f2[(offs1[i] >> 1) + lane]);
        float2 v2 = __half22float2(f2[(offs2[i] >> 1) + lane]);
        float2 v3 = __half22float2(f2[(offs3[i] >> 1) + lane]);
        float2 r;
        r.x = (v0.x + v1.x + v2.x + v3.x) * 0.25f;
        r.y = (v0.y + v1.y + v2.y + v3.y) * 0.25f;
        rs2[((ml * J_TOT + s * CC) >> 1) + lane] = __float22half2_rn(r);
    }
    __syncthreads();

    // wmma m16n16k16 with double-buffered B fragments (hide L2 latency of d_weffh)
    float* part = (float*)rs;   // aliased AFTER all rs reads complete (sync below)
    {
        int otile = w >> 2, kq = w & 3;
        int ksBase = kq * 36;
        wmma::fragment<wmma::matrix_a, 16, 16, 16, __half, wmma::row_major> af;
        wmma::fragment<wmma::matrix_b, 16, 16, 16, __half, wmma::row_major> bf[2];
        wmma::fragment<wmma::accumulator, 16, 16, 16, float> cf;
        wmma::fill_fragment(cf, 0.0f);
        const __half* wbase = d_weffh + otile * 16;
        wmma::load_matrix_sync(bf[0], wbase + (size_t)(ksBase * 16) * CC, CC);
#pragma unroll 4
        for (int t = 0; t < 36; t++) {
            int cur = t & 1;
            if (t + 1 < 36)
                wmma::load_matrix_sync(bf[cur ^ 1],
                                       wbase + (size_t)((ksBase + t + 1) * 16) * CC, CC);
            wmma::load_matrix_sync(af, rs + (ksBase + t) * 16, J_TOT);
            wmma::mma_sync(cf, af, bf[cur], cf);
        }
        __syncthreads();   // all warps done READING rs; accum lives in registers
        wmma::store_matrix_sync(part + w * 256, cf, 16, wmma::mem_row_major);
    }
    __syncthreads();

    // combine k-quarters + bias -> xp_s[m][o]
    for (int i = tid; i < MB * 64; i += 512) {
        int m = i >> 6, o = i & 63;
        int ot = o >> 4, ol = o & 15;
        float v = part[(ot * 4 + 0) * 256 + m * 16 + ol]
                + part[(ot * 4 + 1) * 256 + m * 16 + ol]
                + part[(ot * 4 + 2) * 256 + m * 16 + ol]
                + part[(ot * 4 + 3) * 256 + m * 16 + ol] + d_beff[o];
        xp_s[i] = v;
    }
    __syncthreads();

    // attention: warp w handles m = m0 + w (16 warps, 16 m's)
    const float* xpw = xp_s + w * 64;
    int pr[4]; bool ok[4];
#pragma unroll
    for (int k = 0; k < 4; k++) {
        int p = lane + 32 * k;
        ok[k] = p < 125;
        pr[k] = ok[k] ? p : 124;
    }
    float sx[4] = {0, 0, 0, 0}, sy[4] = {0, 0, 0, 0};
    for (int c = 0; c < 64; c++) {
        float xc = xpw[c];
        const __half2* row = xf_s + c * 125;
#pragma unroll
        for (int k = 0; k < 4; k++) {
            float2 v = __half22float2(row[pr[k]]);
            sx[k] += xc * v.x;
            sy[k] += xc * v.y;
        }
    }
    float mx = -INFINITY;
#pragma unroll
    for (int k = 0; k < 4; k++) {
        sx[k] = ok[k] ? sx[k] * 0.125f : -INFINITY;
        sy[k] = ok[k] ? sy[k] * 0.125f : -INFINITY;
        mx = fmaxf(mx, fmaxf(sx[k], sy[k]));
    }
    mx = warpMaxf(mx);
    float wx[4], wy[4], wsum = 0.f;
#pragma unroll
    for (int k = 0; k < 4; k++) {
        wx[k] = ok[k] ? expf(sx[k] - mx) : 0.f;
        wy[k] = ok[k] ? expf(sy[k] - mx) : 0.f;
        wsum += wx[k] + wy[k];
    }
    wsum = warpSumf(wsum);
    float inv = 1.0f / wsum;
#pragma unroll
    for (int k = 0; k < 4; k++) { wx[k] *= inv; wy[k] *= inv; }

    for (int c = 0; c < 64; c++) {
        const __half2* row = xf_s + c * 125;
        float a = 0.f;
#pragma unroll
        for (int k = 0; k < 4; k++) {
            float2 v = __half22float2(row[pr[k]]);
            a += wx[k] * v.x + wy[k] * v.y;
        }
        a = warpSumf(a);
        if (lane == 0) g_buf[w * 64 + c] = a;
    }
    __syncthreads();
    for (int i = tid; i < MB * 64; i += 512) {
        int ml = i >> 6, c = i & 63;
        d_g[(size_t)(m0 + ml) * CC + c] = g_buf[i];
    }
}

// ==================== kE3: conv1x1 + relu + residual (round-11 best) ===============
// grid (32, 8), 512 threads: 16 warps = 8 o's x 2 K-halves.
__global__ void kE3_out(const float* __restrict__ w1x1, const float* __restrict__ b1x1,
                        const float* __restrict__ prior, float* __restrict__ out) {
    __shared__ float g_s[4096];
    __shared__ float part_s[16];
    __shared__ float gr_s[8];
    int b = blockIdx.x, og = blockIdx.y;
    int tid = threadIdx.x, w = tid >> 5, lid = tid & 31;
    const float4* gsrc = (const float4*)(d_g + (size_t)b * 4096);
#pragma unroll
    for (int i = tid; i < 1024; i += 512) ((float4*)g_s)[i] = gsrc[i];
    __syncthreads();
    int ol = w >> 1, kh = w & 1;
    int o = og * 8 + ol;
    const float4* wr = (const float4*)(w1x1 + (size_t)o * 4096) + kh * 512;
    const float4* gs4 = ((const float4*)g_s) + kh * 512;
    float a = 0.f;
#pragma unroll 4
    for (int j4 = lid; j4 < 512; j4 += 32) {
        float4 wv = wr[j4];
        float4 gv = gs4[j4];
        a += wv.x * gv.x + wv.y * gv.y + wv.z * gv.z + wv.w * gv.w;
    }
    a = warpSumf(a);
    if (lid == 0) part_s[w] = a;
    __syncthreads();
    if (tid < 8)
        gr_s[tid] = fmaxf(part_s[2 * tid] + part_s[2 * tid + 1] + b1x1[og * 8 + tid], 0.f);
    __syncthreads();
    for (int e = tid; e < 8 * PE; e += 512) {
        int jl = e / PE, t = e - jl * PE;
        size_t idx = (size_t)b * (64 * PE) + (size_t)(og * 8 + jl) * PE + t;
        out[idx] = gr_s[jl] + prior[idx];
    }
}

// ---------------- host launcher ----------------------------------------------------
extern "C" void kernel_launch(void* const* d_in, const int* in_sizes, int n_in,
                              void* d_out, int out_size) {
    const float* feature = (const float*)d_in[0];
    const float* prior   = (const float*)d_in[1];
    const float* w1      = (const float*)d_in[2];
    const float* b1      = (const float*)d_in[3];
    const float* fw      = (const float*)d_in[4];
    const float* fb      = (const float*)d_in[5];
    const float* w1x1    = (const float*)d_in[6];
    const float* b1x1    = (const float*)d_in[7];
    float* out = (float*)d_out;

    const int kde_smem = 73728 + 32000;   // rs(+part alias) | xf = 105728 B
    cudaFuncSetAttribute(kDE, cudaFuncAttributeMaxDynamicSharedMemorySize, kde_smem);

    k1_feat_and_fold<<<8512, 256>>>(feature, w1, b1, fw);
    k2_reduce<<<2304, 256>>>(fb);
    kDE<<<M_TOT / MB, 512, kde_smem>>>(prior);
    kE3_out<<<dim3(BB, 8), 512>>>(w1x1, b1x1, prior, out);
}

// round 14
// speedup vs baseline: 1.0716x; 1.0589x over previous
#include <cuda_runtime.h>
#include <cuda_fp16.h>
#include <mma.h>
#include <math.h>

using namespace nvcuda;

#define BB 32
#define CC 64
#define FH 80
#define FW 200
#define HW 16000
#define LANES 64
#define SP 36
#define PE 78
#define J_TOT 2304
#define M_TOT 2048
#define MB 16                       // m's per kDE block

// ---------------- scratch ----------------
__device__ __half d_featT[BB * HW * CC];          // (B,H,W,C) fp16
__device__ __half d_pool8h[BB * 2000 * CC];       // partial pool fp16 [b][q][c]
__device__ __half d_xfh[BB * CC * 250];           // pooled context fp16 [b][c][r]
__device__ float  d_weffp[8 * CC * J_TOT];        // fold partials [ck][o][j]
__device__ float  d_beffp[CC * 8];
__device__ __half d_weffh[J_TOT * CC];            // folded weight fp16 [j][o]
__device__ float  d_beff[CC];
__device__ float  d_g[M_TOT * CC];                // attention output [m][c]

__device__ __forceinline__ float warpMaxf(float a) {
#pragma unroll
    for (int off = 16; off > 0; off >>= 1) a = fmaxf(a, __shfl_xor_sync(0xffffffffu, a, off));
    return a;
}
__device__ __forceinline__ float warpSumf(float a) {
#pragma unroll
    for (int off = 16; off > 0; off >>= 1) a += __shfl_xor_sync(0xffffffffu, a, off);
    return a;
}

// ==================== k1: [kC fold | kA transpose+pool] heterogeneous grid =========
__global__ void k1_feat_and_fold(const float* __restrict__ feat,
                                 const float* __restrict__ w1,
                                 const float* __restrict__ b1,
                                 const float* __restrict__ fw) {
    __shared__ float tile[64][65];
    __shared__ float red[256];
    int bid = blockIdx.x;
    int tid = threadIdx.x;

    if (bid >= 512) {
        int ab = bid - 512;
        int bx = ab % 250, b = ab / 250;
        const float4* src = (const float4*)(feat + (size_t)b * CC * HW + bx * 64);
#pragma unroll
        for (int i = tid; i < 1024; i += 256) {
            int c = i >> 4, x4 = i & 15;
            float4 v = src[(size_t)c * (HW / 4) + x4];
            tile[c][x4 * 4 + 0] = v.x; tile[c][x4 * 4 + 1] = v.y;
            tile[c][x4 * 4 + 2] = v.z; tile[c][x4 * 4 + 3] = v.w;
        }
        __syncthreads();
#pragma unroll
        for (int i = tid; i < 512; i += 256) {
            int row = i >> 3, seg = i & 7;
            __align__(16) __half h[8];
#pragma unroll
            for (int j = 0; j < 8; j++) h[j] = __float2half_rn(tile[seg * 8 + j][row]);
            *(uint4*)(d_featT + ((size_t)b * HW + bx * 64 + row) * CC + seg * 8) = *(uint4*)h;
        }
#pragma unroll
        for (int i = tid; i < 512; i += 256) {
            int q = i >> 6, c = i & 63;
            float s = 0.f;
#pragma unroll
            for (int j = 0; j < 8; j++) s += tile[c][q * 8 + j];
            d_pool8h[((size_t)b * 2000 + bx * 8 + q) * CC + c] = __float2half_rn(s);
        }
    } else {
        int o = bid & 63, ck = bid >> 6;
        int cmBase = ck * 8;
        float* fc_s = &tile[0][0];
        fc_s[tid] = fw[o * 2048 + cmBase * 32 + tid];
        __syncthreads();
        int cin = tid & 63, s0 = tid >> 6;
        float acc[9];
#pragma unroll
        for (int it = 0; it < 9; it++) acc[it] = 0.f;
#pragma unroll
        for (int cm8 = 0; cm8 < 8; cm8++) {
            int cm = cmBase + cm8;
            float wv[5];
#pragma unroll
            for (int k = 0; k < 5; k++) wv[k] = __ldg(w1 + (cm * CC + cin) * 5 + k);
            const float* frow = fc_s + cm8 * 32;
#pragma unroll
            for (int it = 0; it < 9; it++) {
                int s = s0 + it * 4;
#pragma unroll
                for (int k = 0; k < 5; k++) {
                    int t = s - k;
                    if ((unsigned)t < 32u) acc[it] += frow[t] * wv[k];
                }
            }
        }
#pragma unroll
        for (int it = 0; it < 9; it++)
            d_weffp[(size_t)ck * (CC * J_TOT) + (size_t)o * J_TOT + (tid + it * 256)] = acc[it];
        red[tid] = fc_s[tid] * b1[cmBase + (tid >> 5)];
        __syncthreads();
        for (int st = 128; st > 0; st >>= 1) {
            if (tid < st) red[tid] += red[tid + st];
            __syncthreads();
        }
        if (tid == 0) d_beffp[o * 8 + ck] = red[0];
    }
}

// ==================== k2: [kC2 weight-reduce | kA2 pool-reduce] ====================
__global__ void k2_reduce(const float* __restrict__ fb) {
    __shared__ float t_s[64][9];
    int bid = blockIdx.x;
    int tid = threadIdx.x;

    if (bid >= 288) {
        int pb = bid - 288;
        int b = pb / 63, rc = pb % 63;
        int rl = tid >> 6, c = tid & 63;
        int r = rc * 4 + rl;
        if (r < 250) {
            int rh = r / 25, rw = r - rh * 25;
            float acc = 0.f;
#pragma unroll
            for (int dh = 0; dh < 8; dh++)
                acc += __half2float(d_pool8h[((size_t)b * 2000 + (rh * 8 + dh) * 25 + rw) * CC + c]);
            d_xfh[((size_t)b * CC + c) * 250 + r] = __float2half_rn(acc * (1.0f / 64.0f));
        }
    } else {
        int jb = bid % 36, og = bid / 36;
#pragma unroll
        for (int i = tid; i < 512; i += 256) {
            int ol = i >> 6, jl = i & 63;
            float a = 0.f;
#pragma unroll
            for (int ck = 0; ck < 8; ck++)
                a += d_weffp[(size_t)ck * (CC * J_TOT) + (size_t)(og * 8 + ol) * J_TOT + jb * 64 + jl];
            t_s[jl][ol] = a;
        }
        __syncthreads();
        {
            int jl = tid >> 2, op = tid & 3;
            __half2 h = __floats2half2_rn(t_s[jl][2 * op], t_s[jl][2 * op + 1]);
            ((__half2*)d_weffh)[(size_t)(jb * 64 + jl) * 32 + og * 4 + op] = h;
        }
        if (jb == 0 && og == 0 && tid < CC) {
            float s = 0.f;
#pragma unroll
            for (int ck = 0; ck < 8; ck++) s += d_beffp[tid * 8 + ck];
            d_beff[tid] = fb[tid] + s;
        }
    }
}

// ==================== kDE: gather + wmma x_p + wmma attention, fused ===============
// 128 blocks, 512 threads (16 warps). Block = 16 m's.
// dyn smem: rs 73728 (epilogue buffers aliased) | xf padded [64][256] half = 32768
__global__ void kDE(const float* __restrict__ prior) {
    extern __shared__ char smraw[];
    __half* rs    = (__half*)smraw;                        // 16*2304*2 = 73728 B
    __half* xfh_s = (__half*)(smraw + 73728);              // 64*256 half = 32768 B
    // epilogue aliases inside rs region (all dead-after-gather):
    float*  part  = (float*)smraw;                         // [16][256] f32 = 16384 B
    __half* xph   = (__half*)(smraw + 16384);              // [16][64]  = 2048 B
    float*  S_s   = (float*)(smraw + 18432);               // [16][256] f32 = 16384 B
    __half* W_s   = (__half*)(smraw + 34816);              // [16][256] half = 8192 B
    float*  part2 = (float*)(smraw + 43008);               // [16][256] f32 = 16384 B
    __shared__ int offs0[576], offs1[576], offs2[576], offs3[576];

    int m0 = blockIdx.x * MB;
    int b = m0 >> 6;
    int tid = threadIdx.x;
    int w = tid >> 5, lane = tid & 31;

    // xf slice, PADDED to 256 halves per c-row (cols 250..255 = 0)
    const __half2* xsrc = (const __half2*)(d_xfh + (size_t)b * (CC * 250));
    __half2* xfd = (__half2*)xfh_s;
#pragma unroll
    for (int i = tid; i < 8192; i += 512) {
        int c = i >> 7, p = i & 127;
        xfd[c * 128 + p] = (p < 125) ? xsrc[c * 125 + p] : __floats2half2_rn(0.f, 0.f);
    }

    // coordinates -> offsets for 16 m x 36 s
    for (int i = tid; i < 576; i += 512) {
        int ml = i / 36, s = i - ml * 36;
        float px = prior[(size_t)(m0 + ml) * PE + 6 + 2 * s];
        float xs = fminf(px * 0.25f, 199.0f);
        int xc = (int)ceilf(xs), xf_ = (int)floorf(xs);
        double py = 319.0 - (320.0 / 71.0) * (double)(2 * s);
        float ys = fminf((float)py * 0.25f, 79.0f);
        int yc = (int)ceilf(ys), yf_ = (int)floorf(ys);
        offs0[i] = (yc * FW + xc) * CC;
        offs1[i] = (yc * FW + xf_) * CC;
        offs2[i] = (yf_ * FW + xc) * CC;
        offs3[i] = (yf_ * FW + xf_) * CC;
    }
    __syncthreads();

    // gather: warp per point-quad, lane = channel-pair
    const __half2* f2 = (const __half2*)(d_featT + (size_t)b * HW * CC);
    __half2* rs2 = (__half2*)rs;
#pragma unroll 4
    for (int i = w; i < 576; i += 16) {
        int ml = i / 36, s = i - ml * 36;
        float2 v0 = __half22float2(f2[(offs0[i] >> 1) + lane]);
        float2 v1 = __half22float2(f2[(offs1[i] >> 1) + lane]);
        float2 v2 = __half22float2(f2[(offs2[i] >> 1) + lane]);
        float2 v3 = __half22float2(f2[(offs3[i] >> 1) + lane]);
        float2 r;
        r.x = (v0.x + v1.x + v2.x + v3.x) * 0.25f;
        r.y = (v0.y + v1.y + v2.y + v3.y) * 0.25f;
        rs2[((ml * J_TOT + s * CC) >> 1) + lane] = __float22half2_rn(r);
    }
    __syncthreads();

    // ---- x_p GEMM: wmma m16n16k16, warp = (otile, kq) -------------------------------
    {
        int otile = w >> 2, kq = w & 3;
        int ksBase = kq * 36;
        wmma::fragment<wmma::matrix_a, 16, 16, 16, __half, wmma::row_major> af;
        wmma::fragment<wmma::matrix_b, 16, 16, 16, __half, wmma::row_major> bf;
        wmma::fragment<wmma::accumulator, 16, 16, 16, float> cf;
        wmma::fill_fragment(cf, 0.0f);
        for (int t = 0; t < 36; t++) {
            int k0 = (ksBase + t) * 16;
            wmma::load_matrix_sync(af, rs + k0, J_TOT);
            wmma::load_matrix_sync(bf, d_weffh + (size_t)k0 * CC + otile * 16, CC);
            wmma::mma_sync(cf, af, bf, cf);
        }
        __syncthreads();   // all warps done READING rs; accum lives in registers
        wmma::store_matrix_sync(part + w * 256, cf, 16, wmma::mem_row_major);
    }
    __syncthreads();

    // combine k-quarters + bias -> xph[m][o] (fp16)
    for (int i = tid; i < MB * 64; i += 512) {
        int m = i >> 6, o = i & 63;
        int ot = o >> 4, ol = o & 15;
        float v = part[(ot * 4 + 0) * 256 + m * 16 + ol]
                + part[(ot * 4 + 1) * 256 + m * 16 + ol]
                + part[(ot * 4 + 2) * 256 + m * 16 + ol]
                + part[(ot * 4 + 3) * 256 + m * 16 + ol] + d_beff[o];
        xph[m * 64 + o] = __float2half_rn(v);
    }
    __syncthreads();

    // ---- S GEMM: S[16][256] = XPh(16x64) @ XF(64x256). warp w -> n-tile w -----------
    {
        wmma::fragment<wmma::matrix_a, 16, 16, 16, __half, wmma::row_major> af;
        wmma::fragment<wmma::matrix_b, 16, 16, 16, __half, wmma::row_major> bf;
        wmma::fragment<wmma::accumulator, 16, 16, 16, float> cf;
        wmma::fill_fragment(cf, 0.0f);
#pragma unroll
        for (int ks = 0; ks < 4; ks++) {
            wmma::load_matrix_sync(af, xph + ks * 16, 64);
            wmma::load_matrix_sync(bf, xfh_s + ks * 16 * 256 + w * 16, 256);
            wmma::mma_sync(cf, af, bf, cf);
        }
        wmma::store_matrix_sync(S_s + w * 16, cf, 256, wmma::mem_row_major);
    }
    __syncthreads();

    // ---- softmax: warp w handles row m = w --------------------------------------------
    {
        int m = w;
        float scv[8];
        float mx = -INFINITY;
#pragma unroll
        for (int k = 0; k < 8; k++) {
            int r = lane + 32 * k;
            scv[k] = (r < 250) ? S_s[m * 256 + r] * 0.125f : -INFINITY;
            mx = fmaxf(mx, scv[k]);
        }
        mx = warpMaxf(mx);
        float e[8], wsum = 0.f;
#pragma unroll
        for (int k = 0; k < 8; k++) {
            int r = lane + 32 * k;
            e[k] = (r < 250) ? expf(scv[k] - mx) : 0.f;
            wsum += e[k];
        }
        wsum = warpSumf(wsum);
        float inv = 1.0f / wsum;
#pragma unroll
        for (int k = 0; k < 8; k++) {
            int r = lane + 32 * k;
            W_s[m * 256 + r] = __float2half_rn(e[k] * inv);
        }
    }
    __syncthreads();

    // ---- G GEMM: G[16][64] = W(16x256) @ V(256x64), V col-major = xfh_s -------------
    {
        int ct = w >> 2, kq = w & 3;
        wmma::fragment<wmma::matrix_a, 16, 16, 16, __half, wmma::row_major> af;
        wmma::fragment<wmma::matrix_b, 16, 16, 16, __half, wmma::col_major> bf;
        wmma::fragment<wmma::accumulator, 16, 16, 16, float> cf;
        wmma::fill_fragment(cf, 0.0f);
#pragma unroll
        for (int t = 0; t < 4; t++) {
            int ks = kq * 4 + t;
            wmma::load_matrix_sync(af, W_s + ks * 16, 256);
            wmma::load_matrix_sync(bf, xfh_s + ct * 16 * 256 + ks * 16, 256);
            wmma::mma_sync(cf, af, bf, cf);
        }
        wmma::store_matrix_sync(part2 + w * 256, cf, 16, wmma::mem_row_major);
    }
    __syncthreads();

    // combine G k-quarters -> d_g
    for (int i = tid; i < MB * 64; i += 512) {
        int m = i >> 6, c = i & 63;
        int ct = c >> 4, cl = c & 15;
        float v = part2[(ct * 4 + 0) * 256 + m * 16 + cl]
                + part2[(ct * 4 + 1) * 256 + m * 16 + cl]
                + part2[(ct * 4 + 2) * 256 + m * 16 + cl]
                + part2[(ct * 4 + 3) * 256 + m * 16 + cl];
        d_g[(size_t)(m0 + m) * CC + c] = v;
    }
}

// ==================== kE3: conv1x1 + relu + residual (round-11 best) ===============
__global__ void kE3_out(const float* __restrict__ w1x1, const float* __restrict__ b1x1,
                        const float* __restrict__ prior, float* __restrict__ out) {
    __shared__ float g_s[4096];
    __shared__ float part_s[16];
    __shared__ float gr_s[8];
    int b = blockIdx.x, og = blockIdx.y;
    int tid = threadIdx.x, w = tid >> 5, lid = tid & 31;
    const float4* gsrc = (const float4*)(d_g + (size_t)b * 4096);
#pragma unroll
    for (int i = tid; i < 1024; i += 512) ((float4*)g_s)[i] = gsrc[i];
    __syncthreads();
    int ol = w >> 1, kh = w & 1;
    int o = og * 8 + ol;
    const float4* wr = (const float4*)(w1x1 + (size_t)o * 4096) + kh * 512;
    const float4* gs4 = ((const float4*)g_s) + kh * 512;
    float a = 0.f;
#pragma unroll 4
    for (int j4 = lid; j4 < 512; j4 += 32) {
        float4 wv = wr[j4];
        float4 gv = gs4[j4];
        a += wv.x * gv.x + wv.y * gv.y + wv.z * gv.z + wv.w * gv.w;
    }
    a = warpSumf(a);
    if (lid == 0) part_s[w] = a;
    __syncthreads();
    if (tid < 8)
        gr_s[tid] = fmaxf(part_s[2 * tid] + part_s[2 * tid + 1] + b1x1[og * 8 + tid], 0.f);
    __syncthreads();
    for (int e = tid; e < 8 * PE; e += 512) {
        int jl = e / PE, t = e - jl * PE;
        size_t idx = (size_t)b * (64 * PE) + (size_t)(og * 8 + jl) * PE + t;
        out[idx] = gr_s[jl] + prior[idx];
    }
}

// ---------------- host launcher ----------------------------------------------------
extern "C" void kernel_launch(void* const* d_in, const int* in_sizes, int n_in,
                              void* d_out, int out_size) {
    const float* feature = (const float*)d_in[0];
    const float* prior   = (const float*)d_in[1];
    const float* w1      = (const float*)d_in[2];
    const float* b1      = (const float*)d_in[3];
    const float* fw      = (const float*)d_in[4];
    const float* fb      = (const float*)d_in[5];
    const float* w1x1    = (const float*)d_in[6];
    const float* b1x1    = (const float*)d_in[7];
    float* out = (float*)d_out;

    const int kde_smem = 73728 + 32768;   // rs(+epilogue alias) | xf padded = 106496 B
    cudaFuncSetAttribute(kDE, cudaFuncAttributeMaxDynamicSharedMemorySize, kde_smem);

    k1_feat_and_fold<<<8512, 256>>>(feature, w1, b1, fw);
    k2_reduce<<<2304, 256>>>(fb);
    kDE<<<M_TOT / MB, 512, kde_smem>>>(prior);
    kE3_out<<<dim3(BB, 8), 512>>>(w1x1, b1x1, prior, out);
}